// round 12
// baseline (speedup 1.0000x reference)
#include <cuda_runtime.h>
#include <cuda_bf16.h>
#include <cstdint>

#define NN 20000
#define EE 320000
#define GG 256
#define N2 (2 * NN)
#define E2 (2 * EE)

// -------- scratch (static device globals; zero-init, no runtime allocation) --------
__device__ float    g_bufS[(N2 + 256) * 80];
__device__ float    g_bufP[(N2 + 256) * 80];
__device__ float    g_bufQ[(N2 + 256) * 160];
__device__ float    g_bufB[(N2 + 256) * 312];
__device__ uint32_t g_hs[(N2 + 256) * 80];
__device__ uint32_t g_ls[(N2 + 256) * 80];
__device__ int      g_work[2 * N2];           // cnt(h1,h2) | fill(h1,h2)
__device__ int      g_offs[2 * (NN + 1)];
__device__ int      g_csr[E2];
__device__ float    g_dinv[N2];
__device__ float    g_pool[2 * GG * 320];
__device__ float    g_xc[GG * 512];
__device__ float    g_t0[2 * GG * 2048];
__device__ float    g_t1[2 * GG * 2048];
__device__ float    g_part[4 * 1048576];      // 4 x 1M-float split-K partial regions

// -------- bf16 split helpers --------
__device__ __forceinline__ void bsplit2(float x, float y, uint32_t& hi, uint32_t& lo) {
    __nv_bfloat162 h = __floats2bfloat162_rn(x, y);
    float rx = x - __bfloat162float(h.x);
    float ry = y - __bfloat162float(h.y);
    __nv_bfloat162 l = __floats2bfloat162_rn(rx, ry);
    hi = *reinterpret_cast<uint32_t*>(&h);
    lo = *reinterpret_cast<uint32_t*>(&l);
}
__device__ __forceinline__ void mma16(float* c, const uint32_t* a, const uint32_t* b) {
    asm("mma.sync.aligned.m16n8k16.row.col.f32.bf16.bf16.f32 "
        "{%0,%1,%2,%3}, {%4,%5,%6,%7}, {%8,%9}, {%0,%1,%2,%3};"
        : "+f"(c[0]), "+f"(c[1]), "+f"(c[2]), "+f"(c[3])
        : "r"(a[0]), "r"(a[1]), "r"(a[2]), "r"(a[3]), "r"(b[0]), "r"(b[1]));
}

// -------- per-half CSR build --------
__global__ void k_count_h(const int* __restrict__ ei, int* __restrict__ cnt) {
    int e = blockIdx.x * blockDim.x + threadIdx.x;
    if (e < EE) atomicAdd(&cnt[ei[EE + e]], 1);
}

__global__ void k_scan_h(const int* __restrict__ cnt, int* __restrict__ offs,
                         float* __restrict__ dinv) {
    const int T = 1024;
    const int IPT = (NN + T - 1) / T;
    __shared__ int s[T];
    int tid = threadIdx.x;
    int base = tid * IPT;
    int local = 0;
    #pragma unroll
    for (int i = 0; i < IPT; i++) {
        int idx = base + i;
        if (idx < NN) {
            int c = cnt[idx];
            local += c;
            dinv[idx] = rsqrtf((float)(c + 1));
        }
    }
    s[tid] = local;
    __syncthreads();
    for (int off = 1; off < T; off <<= 1) {
        int v = 0;
        if (tid >= off) v = s[tid - off];
        __syncthreads();
        if (tid >= off) s[tid] += v;
        __syncthreads();
    }
    int run = (tid == 0) ? 0 : s[tid - 1];
    #pragma unroll
    for (int i = 0; i < IPT; i++) {
        int idx = base + i;
        if (idx < NN) { offs[idx] = run; run += cnt[idx]; }
    }
    if (tid == 0) offs[NN] = s[T - 1];
}

__global__ void k_fill_h(const int* __restrict__ ei, const int* __restrict__ offs,
                         int* __restrict__ fill, int* __restrict__ csr) {
    int e = blockIdx.x * blockDim.x + threadIdx.x;
    if (e >= EE) return;
    int s = ei[e], d = ei[EE + e];
    int p = atomicAdd(&fill[d], 1);
    csr[offs[d] + p] = s;
}

// -------- per-half prep --------
__global__ void k_prep_h(const float* __restrict__ x, const float* __restrict__ dinv,
                         float* __restrict__ out) {
    int i = blockIdx.x * blockDim.x + threadIdx.x;
    if (i >= NN * 80) return;
    int n = i / 80, f = i - n * 80;
    out[i] = (f < 78) ? dinv[n] * x[(size_t)n * 78 + f] : 0.f;
}

// -------- per-half prescaled aggregation -> bf16 hi/lo planes --------
template <int PAIRS, int LDI>
__global__ void k_agg_bf(const float* __restrict__ hp, const int* __restrict__ offs,
                         const int* __restrict__ csr, const float* __restrict__ dinv,
                         uint32_t* __restrict__ hi, uint32_t* __restrict__ lo) {
    const int R = (PAIRS + 31) / 32;
    int warp = (blockIdx.x * blockDim.x + threadIdx.x) >> 5;
    int lane = threadIdx.x & 31;
    if (warp >= NN) return;
    int n = warp;
    const float2* pn = (const float2*)(hp + (size_t)n * LDI);
    float2 acc[R];
    #pragma unroll
    for (int r = 0; r < R; r++) {
        int idx = lane + 32 * r;
        acc[r] = (idx < PAIRS) ? pn[idx] : make_float2(0.f, 0.f);
    }
    int e0 = offs[n], e1 = offs[n + 1];
    int e = e0;
    for (; e + 4 <= e1; e += 4) {
        const float2* p0 = (const float2*)(hp + (size_t)csr[e] * LDI);
        const float2* p1 = (const float2*)(hp + (size_t)csr[e + 1] * LDI);
        const float2* p2 = (const float2*)(hp + (size_t)csr[e + 2] * LDI);
        const float2* p3 = (const float2*)(hp + (size_t)csr[e + 3] * LDI);
        #pragma unroll
        for (int r = 0; r < R; r++) {
            int idx = lane + 32 * r;
            if (idx < PAIRS) {
                float2 a = p0[idx], b = p1[idx], c = p2[idx], d = p3[idx];
                acc[r].x += (a.x + b.x) + (c.x + d.x);
                acc[r].y += (a.y + b.y) + (c.y + d.y);
            }
        }
    }
    for (; e < e1; e++) {
        const float2* p0 = (const float2*)(hp + (size_t)csr[e] * LDI);
        #pragma unroll
        for (int r = 0; r < R; r++) {
            int idx = lane + 32 * r;
            if (idx < PAIRS) {
                float2 a = p0[idx];
                acc[r].x += a.x;
                acc[r].y += a.y;
            }
        }
    }
    float din = dinv[n];
    #pragma unroll
    for (int r = 0; r < R; r++) {
        int idx = lane + 32 * r;
        if (idx < PAIRS) {
            uint32_t h, l;
            bsplit2(din * acc[r].x, din * acc[r].y, h, l);
            hi[(size_t)n * PAIRS + idx] = h;
            lo[(size_t)n * PAIRS + idx] = l;
        }
    }
}

// -------- per-half global max pool --------
__global__ void k_pool_h(const float* __restrict__ h, const int* __restrict__ bat,
                         float* __restrict__ pool) {
    const int CH = 32;
    const int NCH = NN / CH;
    int idx = blockIdx.x * blockDim.x + threadIdx.x;
    if (idx >= NCH * 312) return;
    int f = idx % 312;
    int c = idx / 312;
    int n0 = c * CH;
    int n1 = n0 + CH;
    int curb = bat[n0];
    float m = 0.f;
    for (int n = n0; n < n1; n++) {
        int b = bat[n];
        if (b != curb) {
            atomicMax((int*)&pool[curb * 320 + f], __float_as_int(m));
            curb = b;
            m = 0.f;
        }
        m = fmaxf(m, h[(size_t)n * 312 + f]);
    }
    atomicMax((int*)&pool[curb * 320 + f], __float_as_int(m));
}

// -------- scatter branch-MLP output [2G,128] -> xc[G,512] --------
__global__ void k_scatter(const float* __restrict__ t, float* __restrict__ xc) {
    int i = blockIdx.x * blockDim.x + threadIdx.x;
    if (i >= 2 * GG * 128) return;
    int r = i >> 7, j = i & 127;
    int br = r >> 8;
    int g = r & 255;
    xc[g * 512 + br * 128 + j] = t[i];
}

// -------- L2 row normalize -> ld 960 --------
__global__ void k_norm(const float* __restrict__ cell, float* __restrict__ out) {
    int g = blockIdx.x;
    __shared__ float s[256];
    float ss = 0.f;
    for (int j = threadIdx.x; j < 954; j += 256) {
        float v = cell[g * 954 + j];
        ss += v * v;
    }
    s[threadIdx.x] = ss;
    __syncthreads();
    for (int o = 128; o > 0; o >>= 1) {
        if (threadIdx.x < o) s[threadIdx.x] += s[threadIdx.x + o];
        __syncthreads();
    }
    float inv = 1.f / fmaxf(sqrtf(s[0]), 1e-12f);
    for (int j = threadIdx.x; j < 960; j += 256)
        out[g * 960 + j] = (j < 954) ? cell[g * 954 + j] * inv : 0.f;
}

// -------- zero kernel --------
__global__ void k_zero(int* __restrict__ work, float* __restrict__ pool) {
    int i = blockIdx.x * blockDim.x + threadIdx.x;
    if (i < 2 * N2) work[i] = 0;
    if (i < 2 * GG * 320) pool[i] = 0.f;
}

// ======== tensor-core GEMM: bf16x3 on mma.m16n8k16 ========
// AREDUCE: A = split-K partials of the PREVIOUS gemm (Sa slices, lda = prev N = this Kp);
//          sums slices, adds bias_prev, relu, then bf16-splits. Fuses the reduce kernel.
template <bool RELU, bool PRESCALE, bool SPLITK, bool ASPLIT, bool AREDUCE>
__global__ __launch_bounds__(256)
void k_tgemm(const float* __restrict__ A, int lda,
             const uint32_t* __restrict__ hiA, const uint32_t* __restrict__ loA, int ldu,
             const float* __restrict__ B,
             const float* __restrict__ bias,
             const float* __restrict__ dinv,
             const float* __restrict__ bias_prev, int Sa,
             float* __restrict__ C, int ldc,
             int M, int N, int Kp, int Kr, int Kc) {
    const int BM = 128, BN = 64;
    __shared__ uint32_t Ah[2][8][BM + 8], Al[2][8][BM + 8];
    __shared__ uint32_t Bh[2][8][BN + 8], Bl[2][8][BN + 8];
    int tid = threadIdx.x;
    int lane = tid & 31, wid = tid >> 5;
    int gid = lane >> 2, tq = lane & 3;
    int wm = (wid & 3) * 32, wn = (wid >> 2) * 32;
    int m0 = blockIdx.y * BM, n0 = blockIdx.x * BN;
    int kbeg = SPLITK ? blockIdx.z * Kc : 0;
    int kend = SPLITK ? min(Kp, kbeg + Kc) : Kp;

    int arow = tid & 127;
    int akp = (tid >> 7) * 4;
    const float* Ar = (ASPLIT || AREDUCE) ? nullptr : A + (size_t)(m0 + arow) * lda + kbeg;
    const uint32_t* HiR = ASPLIT ? hiA + (size_t)(m0 + arow) * ldu + (kbeg >> 1) : nullptr;
    const uint32_t* LoR = ASPLIT ? loA + (size_t)(m0 + arow) * ldu + (kbeg >> 1) : nullptr;
    // AREDUCE: base offset of this row, slice stride
    size_t aroff = AREDUCE ? (size_t)(m0 + arow) * lda + kbeg : 0;
    size_t aslice = AREDUCE ? (size_t)M * lda : 0;
    int bn = tid & 63;
    int bkp = tid >> 6;

    float acc[2][4][4];
    #pragma unroll
    for (int i = 0; i < 2; i++)
        #pragma unroll
        for (int j = 0; j < 4; j++)
            #pragma unroll
            for (int r = 0; r < 4; r++) acc[i][j][r] = 0.f;

    int ksteps = (kend - kbeg) / 16;

    // A tile loader for this thread at k-offset k0 (relative to kbeg)
    auto load_a = [&](int k0, float4& a0, float4& a1) {
        if (AREDUCE) {
            a0 = make_float4(0.f, 0.f, 0.f, 0.f);
            a1 = make_float4(0.f, 0.f, 0.f, 0.f);
            size_t o = aroff + k0 + akp * 2;
            for (int s = 0; s < Sa; s++) {
                const float4* p = (const float4*)(A + s * aslice + o);
                float4 u = p[0], v = p[1];
                a0.x += u.x; a0.y += u.y; a0.z += u.z; a0.w += u.w;
                a1.x += v.x; a1.y += v.y; a1.z += v.z; a1.w += v.w;
            }
            int kb = kbeg + k0 + akp * 2;
            a0.x = fmaxf(a0.x + bias_prev[kb + 0], 0.f);
            a0.y = fmaxf(a0.y + bias_prev[kb + 1], 0.f);
            a0.z = fmaxf(a0.z + bias_prev[kb + 2], 0.f);
            a0.w = fmaxf(a0.w + bias_prev[kb + 3], 0.f);
            a1.x = fmaxf(a1.x + bias_prev[kb + 4], 0.f);
            a1.y = fmaxf(a1.y + bias_prev[kb + 5], 0.f);
            a1.z = fmaxf(a1.z + bias_prev[kb + 6], 0.f);
            a1.w = fmaxf(a1.w + bias_prev[kb + 7], 0.f);
        } else {
            a0 = *(const float4*)(Ar + k0 + akp * 2);
            a1 = *(const float4*)(Ar + k0 + akp * 2 + 4);
        }
    };

    {   // prologue
        if (ASPLIT) {
            uint4 h4 = *(const uint4*)(HiR + akp);
            uint4 l4 = *(const uint4*)(LoR + akp);
            Ah[0][akp + 0][arow] = h4.x; Ah[0][akp + 1][arow] = h4.y;
            Ah[0][akp + 2][arow] = h4.z; Ah[0][akp + 3][arow] = h4.w;
            Al[0][akp + 0][arow] = l4.x; Al[0][akp + 1][arow] = l4.y;
            Al[0][akp + 2][arow] = l4.z; Al[0][akp + 3][arow] = l4.w;
        } else {
            float4 a0, a1;
            load_a(0, a0, a1);
            bsplit2(a0.x, a0.y, Ah[0][akp + 0][arow], Al[0][akp + 0][arow]);
            bsplit2(a0.z, a0.w, Ah[0][akp + 1][arow], Al[0][akp + 1][arow]);
            bsplit2(a1.x, a1.y, Ah[0][akp + 2][arow], Al[0][akp + 2][arow]);
            bsplit2(a1.z, a1.w, Ah[0][akp + 3][arow], Al[0][akp + 3][arow]);
        }
        #pragma unroll
        for (int h = 0; h < 2; h++) {
            int kp = bkp + 4 * h;
            int k = kbeg + 2 * kp;
            int nn = n0 + bn;
            float f0 = (k < Kr && nn < N) ? B[(size_t)k * N + nn] : 0.f;
            float f1 = (k + 1 < Kr && nn < N) ? B[(size_t)(k + 1) * N + nn] : 0.f;
            bsplit2(f0, f1, Bh[0][kp][bn], Bl[0][kp][bn]);
        }
    }
    __syncthreads();

    for (int t = 0; t < ksteps; t++) {
        int cur = t & 1;
        bool more = (t + 1 < ksteps);
        float4 pa0, pa1;
        uint4 ph4, pl4;
        float pb[2][2];
        if (more) {
            if (ASPLIT) {
                ph4 = *(const uint4*)(HiR + (t + 1) * 8 + akp);
                pl4 = *(const uint4*)(LoR + (t + 1) * 8 + akp);
            } else {
                load_a((t + 1) * 16, pa0, pa1);
            }
            #pragma unroll
            for (int h = 0; h < 2; h++) {
                int k = kbeg + (t + 1) * 16 + 2 * (bkp + 4 * h);
                int nn = n0 + bn;
                pb[h][0] = (k < Kr && nn < N) ? B[(size_t)k * N + nn] : 0.f;
                pb[h][1] = (k + 1 < Kr && nn < N) ? B[(size_t)(k + 1) * N + nn] : 0.f;
            }
        }

        uint32_t ah[2][4], al[2][4], bh[4][2], bl[4][2];
        #pragma unroll
        for (int mi = 0; mi < 2; mi++) {
            int r = wm + mi * 16 + gid;
            ah[mi][0] = Ah[cur][tq][r];     al[mi][0] = Al[cur][tq][r];
            ah[mi][1] = Ah[cur][tq][r + 8]; al[mi][1] = Al[cur][tq][r + 8];
            ah[mi][2] = Ah[cur][tq + 4][r]; al[mi][2] = Al[cur][tq + 4][r];
            ah[mi][3] = Ah[cur][tq + 4][r + 8]; al[mi][3] = Al[cur][tq + 4][r + 8];
        }
        #pragma unroll
        for (int ni = 0; ni < 4; ni++) {
            int c = wn + ni * 8 + gid;
            bh[ni][0] = Bh[cur][tq][c];     bl[ni][0] = Bl[cur][tq][c];
            bh[ni][1] = Bh[cur][tq + 4][c]; bl[ni][1] = Bl[cur][tq + 4][c];
        }
        #pragma unroll
        for (int mi = 0; mi < 2; mi++)
            #pragma unroll
            for (int ni = 0; ni < 4; ni++) {
                mma16(acc[mi][ni], ah[mi], bh[ni]);
                mma16(acc[mi][ni], al[mi], bh[ni]);
                mma16(acc[mi][ni], ah[mi], bl[ni]);
            }

        if (more) {
            int nxt = cur ^ 1;
            if (ASPLIT) {
                Ah[nxt][akp + 0][arow] = ph4.x; Ah[nxt][akp + 1][arow] = ph4.y;
                Ah[nxt][akp + 2][arow] = ph4.z; Ah[nxt][akp + 3][arow] = ph4.w;
                Al[nxt][akp + 0][arow] = pl4.x; Al[nxt][akp + 1][arow] = pl4.y;
                Al[nxt][akp + 2][arow] = pl4.z; Al[nxt][akp + 3][arow] = pl4.w;
            } else {
                bsplit2(pa0.x, pa0.y, Ah[nxt][akp + 0][arow], Al[nxt][akp + 0][arow]);
                bsplit2(pa0.z, pa0.w, Ah[nxt][akp + 1][arow], Al[nxt][akp + 1][arow]);
                bsplit2(pa1.x, pa1.y, Ah[nxt][akp + 2][arow], Al[nxt][akp + 2][arow]);
                bsplit2(pa1.z, pa1.w, Ah[nxt][akp + 3][arow], Al[nxt][akp + 3][arow]);
            }
            #pragma unroll
            for (int h = 0; h < 2; h++) {
                int kp = bkp + 4 * h;
                bsplit2(pb[h][0], pb[h][1], Bh[nxt][kp][bn], Bl[nxt][kp][bn]);
            }
            __syncthreads();
        }
    }

    #pragma unroll
    for (int mi = 0; mi < 2; mi++) {
        int r0 = m0 + wm + mi * 16 + gid;
        int r1 = r0 + 8;
        float d0 = 1.f, d1 = 1.f;
        if (PRESCALE) {
            if (r0 < M) d0 = dinv[r0];
            if (r1 < M) d1 = dinv[r1];
        }
        #pragma unroll
        for (int ni = 0; ni < 4; ni++) {
            int cc = n0 + wn + ni * 8 + 2 * tq;
            if (cc >= N) continue;
            float* a = acc[mi][ni];
            if (SPLITK) {
                size_t base = (size_t)blockIdx.z * M * N;
                if (r0 < M) *(float2*)&C[base + (size_t)r0 * N + cc] = make_float2(a[0], a[1]);
                if (r1 < M) *(float2*)&C[base + (size_t)r1 * N + cc] = make_float2(a[2], a[3]);
            } else {
                float b0 = bias[cc], b1 = bias[cc + 1];
                float v00 = a[0] + b0, v01 = a[1] + b1;
                float v10 = a[2] + b0, v11 = a[3] + b1;
                if (RELU) {
                    v00 = fmaxf(v00, 0.f); v01 = fmaxf(v01, 0.f);
                    v10 = fmaxf(v10, 0.f); v11 = fmaxf(v11, 0.f);
                }
                if (PRESCALE) { v00 *= d0; v01 *= d0; v10 *= d1; v11 *= d1; }
                if (r0 < M) *(float2*)&C[(size_t)r0 * ldc + cc] = make_float2(v00, v01);
                if (r1 < M) *(float2*)&C[(size_t)r1 * ldc + cc] = make_float2(v10, v11);
            }
        }
    }
}

template <bool RELU>
__global__ void k_reduce(const float* __restrict__ part, int S,
                         const float* __restrict__ bias,
                         float* __restrict__ C, int ldc, int M, int N) {
    int i = blockIdx.x * blockDim.x + threadIdx.x;
    if (i >= M * N) return;
    int m = i / N, n = i % N;
    float v = 0.f;
    for (int s = 0; s < S; s++) v += part[(size_t)s * M * N + i];
    v += bias[n];
    if (RELU) v = fmaxf(v, 0.f);
    C[m * ldc + n] = v;
}

static void gemm_node(const uint32_t* hiA, const uint32_t* loA, int ldu,
                      const float* B, const float* bias, const float* dinv,
                      float* C, int ldc, int M, int N, int Kp, int Kr, bool prescale,
                      cudaStream_t st) {
    dim3 grid((N + 63) / 64, (M + 127) / 128);
    if (prescale)
        k_tgemm<true, true, false, true, false><<<grid, 256, 0, st>>>(nullptr, 0, hiA, loA, ldu, B, bias, dinv, nullptr, 0, C, ldc, M, N, Kp, Kr, Kp);
    else
        k_tgemm<true, false, false, true, false><<<grid, 256, 0, st>>>(nullptr, 0, hiA, loA, ldu, B, bias, dinv, nullptr, 0, C, ldc, M, N, Kp, Kr, Kp);
}

// plain-A split-K GEMM (writes partials); reduce==true appends k_reduce
static void tgemm(const float* A, int lda, const float* B, const float* bias,
                  float* C, int ldc, int M, int N, int Kp, int Kr,
                  int S, bool relu, float* part, cudaStream_t st, bool reduce = true) {
    if (S <= 1) {
        dim3 grid((N + 63) / 64, (M + 127) / 128);
        if (relu)
            k_tgemm<true, false, false, false, false><<<grid, 256, 0, st>>>(A, lda, nullptr, nullptr, 0, B, bias, nullptr, nullptr, 0, C, ldc, M, N, Kp, Kr, Kp);
        else
            k_tgemm<false, false, false, false, false><<<grid, 256, 0, st>>>(A, lda, nullptr, nullptr, 0, B, bias, nullptr, nullptr, 0, C, ldc, M, N, Kp, Kr, Kp);
        return;
    }
    int Kc = ((Kp / S + 15) / 16) * 16;
    if (Kc < 16) Kc = 16;
    int Se = (Kp + Kc - 1) / Kc;
    dim3 grid((N + 63) / 64, (M + 127) / 128, Se);
    k_tgemm<false, false, true, false, false><<<grid, 256, 0, st>>>(A, lda, nullptr, nullptr, 0, B, nullptr, nullptr, nullptr, 0, part, 0, M, N, Kp, Kr, Kc);
    if (reduce) {
        int tot = M * N;
        if (relu) k_reduce<true><<<(tot + 255) / 256, 256, 0, st>>>(part, Se, bias, C, ldc, M, N);
        else      k_reduce<false><<<(tot + 255) / 256, 256, 0, st>>>(part, Se, bias, C, ldc, M, N);
    }
}

// AREDUCE split-K GEMM: A = partialsIn (Sa slices, bias_prev+relu applied), writes partials out
static void tgemm_ar(const float* partIn, int Sa, const float* bias_prev,
                     const float* B, float* partOut, int M, int N, int K,
                     int S, cudaStream_t st) {
    int Kc = ((K / S + 15) / 16) * 16;
    if (Kc < 16) Kc = 16;
    int Se = (K + Kc - 1) / Kc;
    dim3 grid((N + 63) / 64, (M + 127) / 128, Se);
    k_tgemm<false, false, true, false, true><<<grid, 256, 0, st>>>(partIn, K, nullptr, nullptr, 0, B, nullptr, nullptr, bias_prev, Sa, partOut, 0, M, N, K, K, Kc);
}

// -------- final GEMM: reduces Wf3 partials, bias+relu, then x@Wo + bo --------
__global__ void k_wo(const float* __restrict__ part, int S, const float* __restrict__ bias_prev,
                     const float* __restrict__ B, const float* __restrict__ bias,
                     float* __restrict__ C) {
    int g = blockIdx.x * blockDim.x + threadIdx.x;
    if (g >= GG * 2) return;
    int m = g >> 1, n = g & 1;
    float v = 0.f;
    for (int k = 0; k < 128; k++) {
        float a = 0.f;
        for (int s = 0; s < S; s++) a += part[(size_t)s * GG * 128 + m * 128 + k];
        a = fmaxf(a + bias_prev[k], 0.f);
        v += a * B[k * 2 + n];
    }
    C[g] = v + bias[n];
}

extern "C" void kernel_launch(void* const* d_in, const int* in_sizes, int n_in,
                              void* d_out, int out_size) {
    const float* x1   = (const float*)d_in[0];
    const int*   ei1  = (const int*)d_in[1];
    const int*   bat1 = (const int*)d_in[2];
    const float* x2   = (const float*)d_in[3];
    const int*   ei2  = (const int*)d_in[4];
    const int*   bat2 = (const int*)d_in[5];
    const float* cell = (const float*)d_in[6];
    const float* Wc1 = (const float*)d_in[7];  const float* bc1 = (const float*)d_in[8];
    const float* Wc2 = (const float*)d_in[9];  const float* bc2 = (const float*)d_in[10];
    const float* Wc3 = (const float*)d_in[11]; const float* bc3 = (const float*)d_in[12];
    const float* Wg1 = (const float*)d_in[13]; const float* bg1 = (const float*)d_in[14];
    const float* Wg2 = (const float*)d_in[15]; const float* bg2 = (const float*)d_in[16];
    const float* Wr1 = (const float*)d_in[17]; const float* br1 = (const float*)d_in[18];
    const float* Wr2 = (const float*)d_in[19]; const float* br2 = (const float*)d_in[20];
    const float* Wr3 = (const float*)d_in[21]; const float* br3 = (const float*)d_in[22];
    const float* Wf1 = (const float*)d_in[23]; const float* bf1 = (const float*)d_in[24];
    const float* Wf2 = (const float*)d_in[25]; const float* bf2 = (const float*)d_in[26];
    const float* Wf3 = (const float*)d_in[27]; const float* bf3 = (const float*)d_in[28];
    const float* Wo  = (const float*)d_in[29]; const float* bo  = (const float*)d_in[30];
    float* out = (float*)d_out;

    float *bufS, *bufP, *bufQ, *bufB, *dinv, *pool, *xc, *t0, *t1, *part;
    uint32_t *hs, *ls;
    int *work, *offs, *csr;
    cudaGetSymbolAddress((void**)&bufS, g_bufS);
    cudaGetSymbolAddress((void**)&bufP, g_bufP);
    cudaGetSymbolAddress((void**)&bufQ, g_bufQ);
    cudaGetSymbolAddress((void**)&bufB, g_bufB);
    cudaGetSymbolAddress((void**)&hs,   g_hs);
    cudaGetSymbolAddress((void**)&ls,   g_ls);
    cudaGetSymbolAddress((void**)&work, g_work);
    cudaGetSymbolAddress((void**)&offs, g_offs);
    cudaGetSymbolAddress((void**)&csr,  g_csr);
    cudaGetSymbolAddress((void**)&dinv, g_dinv);
    cudaGetSymbolAddress((void**)&pool, g_pool);
    cudaGetSymbolAddress((void**)&xc,   g_xc);
    cudaGetSymbolAddress((void**)&t0,   g_t0);
    cudaGetSymbolAddress((void**)&t1,   g_t1);
    cudaGetSymbolAddress((void**)&part, g_part);

    float* pB1 = part;                   // Wr1 partials (S=2 x 256x2048 = 1M)
    float* pB2 = part + (1 << 20);       // Wr2 partials (S=8 x 256x512 = 1M)
    float* pA1 = part + (2 << 20);       // Wg1 / Wf1 / Wf3 partials
    float* pA2 = part + (3 << 20);       // Wg2 / Wf2 partials

    static cudaStream_t s1 = nullptr, s2 = nullptr;
    static cudaEvent_t evStart, evH2, evBranch, evCell, evZero;
    if (!s1) {
        cudaStreamCreateWithFlags(&s1, cudaStreamNonBlocking);
        cudaStreamCreateWithFlags(&s2, cudaStreamNonBlocking);
        cudaEventCreateWithFlags(&evStart, cudaEventDisableTiming);
        cudaEventCreateWithFlags(&evH2, cudaEventDisableTiming);
        cudaEventCreateWithFlags(&evBranch, cudaEventDisableTiming);
        cudaEventCreateWithFlags(&evCell, cudaEventDisableTiming);
        cudaEventCreateWithFlags(&evZero, cudaEventDisableTiming);
    }

    const int EB = (EE + 255) / 256;
    const int HAGG = (NN * 32 + 255) / 256;
    const int PREPB = (NN * 80 + 255) / 256;
    const int POOLB = ((NN / 32) * 312 + 255) / 256;

    // ======== fork ========
    cudaEventRecord(evStart, 0);

    // ======== stream s2: cell MLP from t=0 (fused reduce chain) ========
    cudaStreamWaitEvent(s2, evStart, 0);
    k_norm<<<GG, 256, 0, s2>>>(cell, t0);
    // Wr1: partials only (S=2), no reduce
    tgemm(t0, 960, Wr1, nullptr, nullptr, 0, GG, 2048, 960, 954, 2, false, pB1, s2, false);
    // Wr2: AREDUCE(pB1, 2, br1) -> partials S=8 in pB2
    tgemm_ar(pB1, 2, br1, Wr2, pB2, GG, 512, 2048, 8, s2);
    // Wr3: AREDUCE(pB2, 8, br2) -> partials S=4 in pB1, then reduce into xc[256:512)
    tgemm_ar(pB2, 8, br2, Wr3, pB1, GG, 256, 512, 4, s2);
    k_reduce<true><<<(GG * 256 + 255) / 256, 256, 0, s2>>>(pB1, 4, br3, xc + 256, 512, GG, 256);
    cudaEventRecord(evCell, s2);

    // ======== per-half full chains (h0 on stream 0, h1 on s1) ========
    cudaStreamWaitEvent(s1, evStart, 0);
    for (int h = 0; h < 2; h++) {
        cudaStream_t st = h ? s1 : 0;
        const float* x  = h ? x2 : x1;
        const int* ei   = h ? ei2 : ei1;
        const int* bat  = h ? bat2 : bat1;
        int* cnt_h  = work + h * NN;
        int* fill_h = work + N2 + h * NN;
        int* offs_h = offs + h * (NN + 1);
        int* csr_h  = csr + h * EE;
        float* dinv_h = dinv + h * NN;
        float* bufS_h = bufS + (size_t)h * NN * 80;
        float* bufP_h = bufP + (size_t)h * NN * 80;
        float* bufQ_h = bufQ + (size_t)h * NN * 160;
        float* bufB_h = bufB + (size_t)h * NN * 312;
        uint32_t* hs_h = hs + (size_t)h * NN * 80;
        uint32_t* ls_h = ls + (size_t)h * NN * 80;
        float* pool_h = pool + (size_t)h * GG * 320;

        k_count_h<<<EB, 256, 0, st>>>(ei, cnt_h);
        k_scan_h<<<1, 1024, 0, st>>>(cnt_h, offs_h, dinv_h);
        k_fill_h<<<EB, 256, 0, st>>>(ei, offs_h, fill_h, csr_h);
        k_prep_h<<<PREPB, 256, 0, st>>>(x, dinv_h, bufS_h);

        k_agg_bf<40, 80><<<HAGG, 256, 0, st>>>(bufS_h, offs_h, csr_h, dinv_h, hs_h, ls_h);
        gemm_node(hs_h, ls_h, 40, Wc1, bc1, dinv_h, bufP_h, 80, NN, 78, 80, 78, true, st);
        k_agg_bf<40, 80><<<HAGG, 256, 0, st>>>(bufP_h, offs_h, csr_h, dinv_h, hs_h, ls_h);
        gemm_node(hs_h, ls_h, 40, Wc2, bc2, dinv_h, bufQ_h, 160, NN, 156, 80, 78, true, st);
        k_agg_bf<80, 160><<<HAGG, 256, 0, st>>>(bufQ_h, offs_h, csr_h, dinv_h, hs_h, ls_h);
        gemm_node(hs_h, ls_h, 80, Wc3, bc3, dinv_h, bufB_h, 312, NN, 312, 160, 156, false, st);

        k_pool_h<<<POOLB, 256, 0, st>>>(bufB_h, bat, pool_h);
    }
    cudaEventRecord(evH2, s1);
    cudaStreamWaitEvent(0, evH2, 0);

    // ---- branch MLP batched (M = 512): gemm+reduce (K not 16-aligned for fusion)
    float* tb0 = t0 + GG * 2048;
    float* tb1 = t1 + GG * 2048;
    tgemm(pool, 320, Wg1, bg1, tb0, 160, 2 * GG, 156, 320, 312, 4, true, pA1, 0);
    cudaEventRecord(evBranch, 0);
    tgemm(tb0, 160, Wg2, bg2, tb1, 128, 2 * GG, 128, 160, 156, 4, false, pA2, 0);
    k_scatter<<<(2 * GG * 128 + 255) / 256, 256>>>(tb1, xc);

    // ======== stream s2: zero work+pool after branch MLP consumed pool ========
    cudaStreamWaitEvent(s2, evBranch, 0);
    k_zero<<<(2 * GG * 320 + 255) / 256, 256, 0, s2>>>(work, pool);
    cudaEventRecord(evZero, s2);

    // ======== stream 0: head MLP (fused reduce chain) ========
    cudaStreamWaitEvent(0, evCell, 0);
    // Wf1: partials only (S=4) -> pA1
    tgemm(xc, 512, Wf1, nullptr, nullptr, 0, GG, 1024, 512, 512, 4, false, pA1, 0, false);
    // Wf2: AREDUCE(pA1, 4, bf1) -> partials S=8 -> pA2
    tgemm_ar(pA1, 4, bf1, Wf2, pA2, GG, 512, 1024, 8, 0);
    // Wf3: AREDUCE(pA2, 8, bf2) -> partials S=8 -> pA1
    tgemm_ar(pA2, 8, bf2, Wf3, pA1, GG, 128, 512, 8, 0);
    // Wo: reduce pA1 (8 slices) + bf3 + relu, then @Wo + bo
    k_wo<<<(GG * 2 + 255) / 256, 256>>>(pA1, 8, bf3, Wo, bo, out);

    // ---- join
    cudaStreamWaitEvent(0, evZero, 0);
}

// round 13
// speedup vs baseline: 1.2849x; 1.2849x over previous
#include <cuda_runtime.h>
#include <cuda_bf16.h>
#include <cstdint>

#define NN 20000
#define EE 320000
#define GG 256
#define N2 (2 * NN)
#define E2 (2 * EE)

// -------- scratch (static device globals; zero-init, no runtime allocation) --------
__device__ float    g_bufS[(N2 + 256) * 80];
__device__ float    g_bufP[(N2 + 256) * 80];
__device__ float    g_bufQ[(N2 + 256) * 160];
__device__ float    g_bufB[(N2 + 256) * 312];
__device__ uint32_t g_hs[(N2 + 256) * 80];
__device__ uint32_t g_ls[(N2 + 256) * 80];
__device__ int      g_work[2 * N2];           // cnt(h1,h2) | fill(h1,h2)
__device__ int      g_offs[2 * (NN + 1)];
__device__ int      g_csr[E2];
__device__ float    g_dinv[N2];
__device__ float    g_pool[2 * GG * 320];
__device__ float    g_xc[GG * 512];
__device__ float    g_t0[2 * GG * 2048];
__device__ float    g_t1[2 * GG * 2048];
__device__ float    g_part[4 * 1048576];

// -------- bf16 split helpers --------
__device__ __forceinline__ void bsplit2(float x, float y, uint32_t& hi, uint32_t& lo) {
    __nv_bfloat162 h = __floats2bfloat162_rn(x, y);
    float rx = x - __bfloat162float(h.x);
    float ry = y - __bfloat162float(h.y);
    __nv_bfloat162 l = __floats2bfloat162_rn(rx, ry);
    hi = *reinterpret_cast<uint32_t*>(&h);
    lo = *reinterpret_cast<uint32_t*>(&l);
}
__device__ __forceinline__ void mma16(float* c, const uint32_t* a, const uint32_t* b) {
    asm("mma.sync.aligned.m16n8k16.row.col.f32.bf16.bf16.f32 "
        "{%0,%1,%2,%3}, {%4,%5,%6,%7}, {%8,%9}, {%0,%1,%2,%3};"
        : "+f"(c[0]), "+f"(c[1]), "+f"(c[2]), "+f"(c[3])
        : "r"(a[0]), "r"(a[1]), "r"(a[2]), "r"(a[3]), "r"(b[0]), "r"(b[1]));
}

// -------- per-half CSR build --------
__global__ void k_count_h(const int* __restrict__ ei, int* __restrict__ cnt) {
    int e = blockIdx.x * blockDim.x + threadIdx.x;
    if (e < EE) atomicAdd(&cnt[ei[EE + e]], 1);
}

__global__ void k_scan_h(const int* __restrict__ cnt, int* __restrict__ offs,
                         float* __restrict__ dinv) {
    const int T = 1024;
    const int IPT = (NN + T - 1) / T;
    __shared__ int s[T];
    int tid = threadIdx.x;
    int base = tid * IPT;
    int local = 0;
    #pragma unroll
    for (int i = 0; i < IPT; i++) {
        int idx = base + i;
        if (idx < NN) {
            int c = cnt[idx];
            local += c;
            dinv[idx] = rsqrtf((float)(c + 1));
        }
    }
    s[tid] = local;
    __syncthreads();
    for (int off = 1; off < T; off <<= 1) {
        int v = 0;
        if (tid >= off) v = s[tid - off];
        __syncthreads();
        if (tid >= off) s[tid] += v;
        __syncthreads();
    }
    int run = (tid == 0) ? 0 : s[tid - 1];
    #pragma unroll
    for (int i = 0; i < IPT; i++) {
        int idx = base + i;
        if (idx < NN) { offs[idx] = run; run += cnt[idx]; }
    }
    if (tid == 0) offs[NN] = s[T - 1];
}

__global__ void k_fill_h(const int* __restrict__ ei, const int* __restrict__ offs,
                         int* __restrict__ fill, int* __restrict__ csr) {
    int e = blockIdx.x * blockDim.x + threadIdx.x;
    if (e >= EE) return;
    int s = ei[e], d = ei[EE + e];
    int p = atomicAdd(&fill[d], 1);
    csr[offs[d] + p] = s;
}

// -------- per-half prep --------
__global__ void k_prep_h(const float* __restrict__ x, const float* __restrict__ dinv,
                         float* __restrict__ out) {
    int i = blockIdx.x * blockDim.x + threadIdx.x;
    if (i >= NN * 80) return;
    int n = i / 80, f = i - n * 80;
    out[i] = (f < 78) ? dinv[n] * x[(size_t)n * 78 + f] : 0.f;
}

// -------- per-half prescaled aggregation -> bf16 hi/lo planes --------
template <int PAIRS, int LDI>
__global__ void k_agg_bf(const float* __restrict__ hp, const int* __restrict__ offs,
                         const int* __restrict__ csr, const float* __restrict__ dinv,
                         uint32_t* __restrict__ hi, uint32_t* __restrict__ lo) {
    const int R = (PAIRS + 31) / 32;
    int warp = (blockIdx.x * blockDim.x + threadIdx.x) >> 5;
    int lane = threadIdx.x & 31;
    if (warp >= NN) return;
    int n = warp;
    const float2* pn = (const float2*)(hp + (size_t)n * LDI);
    float2 acc[R];
    #pragma unroll
    for (int r = 0; r < R; r++) {
        int idx = lane + 32 * r;
        acc[r] = (idx < PAIRS) ? pn[idx] : make_float2(0.f, 0.f);
    }
    int e0 = offs[n], e1 = offs[n + 1];
    int e = e0;
    for (; e + 4 <= e1; e += 4) {
        const float2* p0 = (const float2*)(hp + (size_t)csr[e] * LDI);
        const float2* p1 = (const float2*)(hp + (size_t)csr[e + 1] * LDI);
        const float2* p2 = (const float2*)(hp + (size_t)csr[e + 2] * LDI);
        const float2* p3 = (const float2*)(hp + (size_t)csr[e + 3] * LDI);
        #pragma unroll
        for (int r = 0; r < R; r++) {
            int idx = lane + 32 * r;
            if (idx < PAIRS) {
                float2 a = p0[idx], b = p1[idx], c = p2[idx], d = p3[idx];
                acc[r].x += (a.x + b.x) + (c.x + d.x);
                acc[r].y += (a.y + b.y) + (c.y + d.y);
            }
        }
    }
    for (; e < e1; e++) {
        const float2* p0 = (const float2*)(hp + (size_t)csr[e] * LDI);
        #pragma unroll
        for (int r = 0; r < R; r++) {
            int idx = lane + 32 * r;
            if (idx < PAIRS) {
                float2 a = p0[idx];
                acc[r].x += a.x;
                acc[r].y += a.y;
            }
        }
    }
    float din = dinv[n];
    #pragma unroll
    for (int r = 0; r < R; r++) {
        int idx = lane + 32 * r;
        if (idx < PAIRS) {
            uint32_t h, l;
            bsplit2(din * acc[r].x, din * acc[r].y, h, l);
            hi[(size_t)n * PAIRS + idx] = h;
            lo[(size_t)n * PAIRS + idx] = l;
        }
    }
}

// -------- per-half global max pool --------
__global__ void k_pool_h(const float* __restrict__ h, const int* __restrict__ bat,
                         float* __restrict__ pool) {
    const int CH = 32;
    const int NCH = NN / CH;
    int idx = blockIdx.x * blockDim.x + threadIdx.x;
    if (idx >= NCH * 312) return;
    int f = idx % 312;
    int c = idx / 312;
    int n0 = c * CH;
    int n1 = n0 + CH;
    int curb = bat[n0];
    float m = 0.f;
    for (int n = n0; n < n1; n++) {
        int b = bat[n];
        if (b != curb) {
            atomicMax((int*)&pool[curb * 320 + f], __float_as_int(m));
            curb = b;
            m = 0.f;
        }
        m = fmaxf(m, h[(size_t)n * 312 + f]);
    }
    atomicMax((int*)&pool[curb * 320 + f], __float_as_int(m));
}

// -------- L2 row normalize -> ld 960 --------
__global__ void k_norm(const float* __restrict__ cell, float* __restrict__ out) {
    int g = blockIdx.x;
    __shared__ float s[256];
    float ss = 0.f;
    for (int j = threadIdx.x; j < 954; j += 256) {
        float v = cell[g * 954 + j];
        ss += v * v;
    }
    s[threadIdx.x] = ss;
    __syncthreads();
    for (int o = 128; o > 0; o >>= 1) {
        if (threadIdx.x < o) s[threadIdx.x] += s[threadIdx.x + o];
        __syncthreads();
    }
    float inv = 1.f / fmaxf(sqrtf(s[0]), 1e-12f);
    for (int j = threadIdx.x; j < 960; j += 256)
        out[g * 960 + j] = (j < 954) ? cell[g * 954 + j] * inv : 0.f;
}

// -------- zero kernel --------
__global__ void k_zero(int* __restrict__ work, float* __restrict__ pool) {
    int i = blockIdx.x * blockDim.x + threadIdx.x;
    if (i < 2 * N2) work[i] = 0;
    if (i < 2 * GG * 320) pool[i] = 0.f;
}

// ======== tensor-core GEMM: bf16x3 on mma.m16n8k16 (R11 version, no AREDUCE) ========
template <bool RELU, bool PRESCALE, bool SPLITK, bool ASPLIT>
__global__ __launch_bounds__(256)
void k_tgemm(const float* __restrict__ A, int lda,
             const uint32_t* __restrict__ hiA, const uint32_t* __restrict__ loA, int ldu,
             const float* __restrict__ B,
             const float* __restrict__ bias,
             const float* __restrict__ dinv,
             float* __restrict__ C, int ldc,
             int M, int N, int Kp, int Kr, int Kc) {
    const int BM = 128, BN = 64;
    __shared__ uint32_t Ah[2][8][BM + 8], Al[2][8][BM + 8];
    __shared__ uint32_t Bh[2][8][BN + 8], Bl[2][8][BN + 8];
    int tid = threadIdx.x;
    int lane = tid & 31, wid = tid >> 5;
    int gid = lane >> 2, tq = lane & 3;
    int wm = (wid & 3) * 32, wn = (wid >> 2) * 32;
    int m0 = blockIdx.y * BM, n0 = blockIdx.x * BN;
    int kbeg = SPLITK ? blockIdx.z * Kc : 0;
    int kend = SPLITK ? min(Kp, kbeg + Kc) : Kp;

    int arow = tid & 127;
    int akp = (tid >> 7) * 4;
    const float* Ar = ASPLIT ? nullptr : A + (size_t)(m0 + arow) * lda + kbeg;
    const uint32_t* HiR = ASPLIT ? hiA + (size_t)(m0 + arow) * ldu + (kbeg >> 1) : nullptr;
    const uint32_t* LoR = ASPLIT ? loA + (size_t)(m0 + arow) * ldu + (kbeg >> 1) : nullptr;
    int bn = tid & 63;
    int bkp = tid >> 6;

    float acc[2][4][4];
    #pragma unroll
    for (int i = 0; i < 2; i++)
        #pragma unroll
        for (int j = 0; j < 4; j++)
            #pragma unroll
            for (int r = 0; r < 4; r++) acc[i][j][r] = 0.f;

    int ksteps = (kend - kbeg) / 16;

    {
        if (ASPLIT) {
            uint4 h4 = *(const uint4*)(HiR + akp);
            uint4 l4 = *(const uint4*)(LoR + akp);
            Ah[0][akp + 0][arow] = h4.x; Ah[0][akp + 1][arow] = h4.y;
            Ah[0][akp + 2][arow] = h4.z; Ah[0][akp + 3][arow] = h4.w;
            Al[0][akp + 0][arow] = l4.x; Al[0][akp + 1][arow] = l4.y;
            Al[0][akp + 2][arow] = l4.z; Al[0][akp + 3][arow] = l4.w;
        } else {
            float4 a0 = *(const float4*)(Ar + akp * 2);
            float4 a1 = *(const float4*)(Ar + akp * 2 + 4);
            bsplit2(a0.x, a0.y, Ah[0][akp + 0][arow], Al[0][akp + 0][arow]);
            bsplit2(a0.z, a0.w, Ah[0][akp + 1][arow], Al[0][akp + 1][arow]);
            bsplit2(a1.x, a1.y, Ah[0][akp + 2][arow], Al[0][akp + 2][arow]);
            bsplit2(a1.z, a1.w, Ah[0][akp + 3][arow], Al[0][akp + 3][arow]);
        }
        #pragma unroll
        for (int h = 0; h < 2; h++) {
            int kp = bkp + 4 * h;
            int k = kbeg + 2 * kp;
            int nn = n0 + bn;
            float f0 = (k < Kr && nn < N) ? B[(size_t)k * N + nn] : 0.f;
            float f1 = (k + 1 < Kr && nn < N) ? B[(size_t)(k + 1) * N + nn] : 0.f;
            bsplit2(f0, f1, Bh[0][kp][bn], Bl[0][kp][bn]);
        }
    }
    __syncthreads();

    for (int t = 0; t < ksteps; t++) {
        int cur = t & 1;
        bool more = (t + 1 < ksteps);
        float4 pa0, pa1;
        uint4 ph4, pl4;
        float pb[2][2];
        if (more) {
            if (ASPLIT) {
                ph4 = *(const uint4*)(HiR + (t + 1) * 8 + akp);
                pl4 = *(const uint4*)(LoR + (t + 1) * 8 + akp);
            } else {
                int k0 = (t + 1) * 16;
                pa0 = *(const float4*)(Ar + k0 + akp * 2);
                pa1 = *(const float4*)(Ar + k0 + akp * 2 + 4);
            }
            #pragma unroll
            for (int h = 0; h < 2; h++) {
                int k = kbeg + (t + 1) * 16 + 2 * (bkp + 4 * h);
                int nn = n0 + bn;
                pb[h][0] = (k < Kr && nn < N) ? B[(size_t)k * N + nn] : 0.f;
                pb[h][1] = (k + 1 < Kr && nn < N) ? B[(size_t)(k + 1) * N + nn] : 0.f;
            }
        }

        uint32_t ah[2][4], al[2][4], bh[4][2], bl[4][2];
        #pragma unroll
        for (int mi = 0; mi < 2; mi++) {
            int r = wm + mi * 16 + gid;
            ah[mi][0] = Ah[cur][tq][r];     al[mi][0] = Al[cur][tq][r];
            ah[mi][1] = Ah[cur][tq][r + 8]; al[mi][1] = Al[cur][tq][r + 8];
            ah[mi][2] = Ah[cur][tq + 4][r]; al[mi][2] = Al[cur][tq + 4][r];
            ah[mi][3] = Ah[cur][tq + 4][r + 8]; al[mi][3] = Al[cur][tq + 4][r + 8];
        }
        #pragma unroll
        for (int ni = 0; ni < 4; ni++) {
            int c = wn + ni * 8 + gid;
            bh[ni][0] = Bh[cur][tq][c];     bl[ni][0] = Bl[cur][tq][c];
            bh[ni][1] = Bh[cur][tq + 4][c]; bl[ni][1] = Bl[cur][tq + 4][c];
        }
        #pragma unroll
        for (int mi = 0; mi < 2; mi++)
            #pragma unroll
            for (int ni = 0; ni < 4; ni++) {
                mma16(acc[mi][ni], ah[mi], bh[ni]);
                mma16(acc[mi][ni], al[mi], bh[ni]);
                mma16(acc[mi][ni], ah[mi], bl[ni]);
            }

        if (more) {
            int nxt = cur ^ 1;
            if (ASPLIT) {
                Ah[nxt][akp + 0][arow] = ph4.x; Ah[nxt][akp + 1][arow] = ph4.y;
                Ah[nxt][akp + 2][arow] = ph4.z; Ah[nxt][akp + 3][arow] = ph4.w;
                Al[nxt][akp + 0][arow] = pl4.x; Al[nxt][akp + 1][arow] = pl4.y;
                Al[nxt][akp + 2][arow] = pl4.z; Al[nxt][akp + 3][arow] = pl4.w;
            } else {
                bsplit2(pa0.x, pa0.y, Ah[nxt][akp + 0][arow], Al[nxt][akp + 0][arow]);
                bsplit2(pa0.z, pa0.w, Ah[nxt][akp + 1][arow], Al[nxt][akp + 1][arow]);
                bsplit2(pa1.x, pa1.y, Ah[nxt][akp + 2][arow], Al[nxt][akp + 2][arow]);
                bsplit2(pa1.z, pa1.w, Ah[nxt][akp + 3][arow], Al[nxt][akp + 3][arow]);
            }
            #pragma unroll
            for (int h = 0; h < 2; h++) {
                int kp = bkp + 4 * h;
                bsplit2(pb[h][0], pb[h][1], Bh[nxt][kp][bn], Bl[nxt][kp][bn]);
            }
            __syncthreads();
        }
    }

    #pragma unroll
    for (int mi = 0; mi < 2; mi++) {
        int r0 = m0 + wm + mi * 16 + gid;
        int r1 = r0 + 8;
        float d0 = 1.f, d1 = 1.f;
        if (PRESCALE) {
            if (r0 < M) d0 = dinv[r0];
            if (r1 < M) d1 = dinv[r1];
        }
        #pragma unroll
        for (int ni = 0; ni < 4; ni++) {
            int cc = n0 + wn + ni * 8 + 2 * tq;
            if (cc >= N) continue;
            float* a = acc[mi][ni];
            if (SPLITK) {
                size_t base = (size_t)blockIdx.z * M * N;
                if (r0 < M) *(float2*)&C[base + (size_t)r0 * N + cc] = make_float2(a[0], a[1]);
                if (r1 < M) *(float2*)&C[base + (size_t)r1 * N + cc] = make_float2(a[2], a[3]);
            } else {
                float b0 = bias[cc], b1 = bias[cc + 1];
                float v00 = a[0] + b0, v01 = a[1] + b1;
                float v10 = a[2] + b0, v11 = a[3] + b1;
                if (RELU) {
                    v00 = fmaxf(v00, 0.f); v01 = fmaxf(v01, 0.f);
                    v10 = fmaxf(v10, 0.f); v11 = fmaxf(v11, 0.f);
                }
                if (PRESCALE) { v00 *= d0; v01 *= d0; v10 *= d1; v11 *= d1; }
                if (r0 < M) *(float2*)&C[(size_t)r0 * ldc + cc] = make_float2(v00, v01);
                if (r1 < M) *(float2*)&C[(size_t)r1 * ldc + cc] = make_float2(v10, v11);
            }
        }
    }
}

template <bool RELU>
__global__ void k_reduce(const float* __restrict__ part, int S,
                         const float* __restrict__ bias,
                         float* __restrict__ C, int ldc, int M, int N) {
    int i = blockIdx.x * blockDim.x + threadIdx.x;
    if (i >= M * N) return;
    int m = i / N, n = i % N;
    float v = 0.f;
    for (int s = 0; s < S; s++) v += part[(size_t)s * M * N + i];
    v += bias[n];
    if (RELU) v = fmaxf(v, 0.f);
    C[m * ldc + n] = v;
}

// reduce Wg2 partials [2G,128] and scatter into xc[G,512] in one pass
__global__ void k_reduce_scat(const float* __restrict__ part, int S,
                              const float* __restrict__ bias,
                              float* __restrict__ xc) {
    int i = blockIdx.x * blockDim.x + threadIdx.x;
    if (i >= 2 * GG * 128) return;
    int m = i >> 7, j = i & 127;
    float v = 0.f;
    for (int s = 0; s < S; s++) v += part[(size_t)s * 2 * GG * 128 + i];
    v += bias[j];
    int g = m & 255, br = m >> 8;
    xc[g * 512 + br * 128 + j] = v;
}

static void gemm_node(const uint32_t* hiA, const uint32_t* loA, int ldu,
                      const float* B, const float* bias, const float* dinv,
                      float* C, int ldc, int M, int N, int Kp, int Kr, bool prescale,
                      cudaStream_t st) {
    dim3 grid((N + 63) / 64, (M + 127) / 128);
    if (prescale)
        k_tgemm<true, true, false, true><<<grid, 256, 0, st>>>(nullptr, 0, hiA, loA, ldu, B, bias, dinv, C, ldc, M, N, Kp, Kr, Kp);
    else
        k_tgemm<true, false, false, true><<<grid, 256, 0, st>>>(nullptr, 0, hiA, loA, ldu, B, bias, dinv, C, ldc, M, N, Kp, Kr, Kp);
}

static void tgemm(const float* A, int lda, const float* B, const float* bias,
                  float* C, int ldc, int M, int N, int Kp, int Kr,
                  int S, bool relu, float* part, cudaStream_t st, bool reduce = true) {
    if (S <= 1) {
        dim3 grid((N + 63) / 64, (M + 127) / 128);
        if (relu)
            k_tgemm<true, false, false, false><<<grid, 256, 0, st>>>(A, lda, nullptr, nullptr, 0, B, bias, nullptr, C, ldc, M, N, Kp, Kr, Kp);
        else
            k_tgemm<false, false, false, false><<<grid, 256, 0, st>>>(A, lda, nullptr, nullptr, 0, B, bias, nullptr, C, ldc, M, N, Kp, Kr, Kp);
        return;
    }
    int Kc = ((Kp / S + 15) / 16) * 16;
    if (Kc < 16) Kc = 16;
    int Se = (Kp + Kc - 1) / Kc;
    dim3 grid((N + 63) / 64, (M + 127) / 128, Se);
    k_tgemm<false, false, true, false><<<grid, 256, 0, st>>>(A, lda, nullptr, nullptr, 0, B, nullptr, nullptr, part, 0, M, N, Kp, Kr, Kc);
    if (reduce) {
        int tot = M * N;
        if (relu) k_reduce<true><<<(tot + 255) / 256, 256, 0, st>>>(part, Se, bias, C, ldc, M, N);
        else      k_reduce<false><<<(tot + 255) / 256, 256, 0, st>>>(part, Se, bias, C, ldc, M, N);
    }
}

// -------- tiny scalar GEMM for the final 256x2x128 --------
__global__ void k_wo(const float* __restrict__ A, const float* __restrict__ B,
                     const float* __restrict__ bias, float* __restrict__ C) {
    int g = blockIdx.x * blockDim.x + threadIdx.x;
    if (g >= GG * 2) return;
    int m = g >> 1, n = g & 1;
    float v = 0.f;
    const float* a = A + m * 128;
    for (int k = 0; k < 128; k++) v += a[k] * B[k * 2 + n];
    C[g] = v + bias[n];
}

extern "C" void kernel_launch(void* const* d_in, const int* in_sizes, int n_in,
                              void* d_out, int out_size) {
    const float* x1   = (const float*)d_in[0];
    const int*   ei1  = (const int*)d_in[1];
    const int*   bat1 = (const int*)d_in[2];
    const float* x2   = (const float*)d_in[3];
    const int*   ei2  = (const int*)d_in[4];
    const int*   bat2 = (const int*)d_in[5];
    const float* cell = (const float*)d_in[6];
    const float* Wc1 = (const float*)d_in[7];  const float* bc1 = (const float*)d_in[8];
    const float* Wc2 = (const float*)d_in[9];  const float* bc2 = (const float*)d_in[10];
    const float* Wc3 = (const float*)d_in[11]; const float* bc3 = (const float*)d_in[12];
    const float* Wg1 = (const float*)d_in[13]; const float* bg1 = (const float*)d_in[14];
    const float* Wg2 = (const float*)d_in[15]; const float* bg2 = (const float*)d_in[16];
    const float* Wr1 = (const float*)d_in[17]; const float* br1 = (const float*)d_in[18];
    const float* Wr2 = (const float*)d_in[19]; const float* br2 = (const float*)d_in[20];
    const float* Wr3 = (const float*)d_in[21]; const float* br3 = (const float*)d_in[22];
    const float* Wf1 = (const float*)d_in[23]; const float* bf1 = (const float*)d_in[24];
    const float* Wf2 = (const float*)d_in[25]; const float* bf2 = (const float*)d_in[26];
    const float* Wf3 = (const float*)d_in[27]; const float* bf3 = (const float*)d_in[28];
    const float* Wo  = (const float*)d_in[29]; const float* bo  = (const float*)d_in[30];
    float* out = (float*)d_out;

    float *bufS, *bufP, *bufQ, *bufB, *dinv, *pool, *xc, *t0, *t1, *part;
    uint32_t *hs, *ls;
    int *work, *offs, *csr;
    cudaGetSymbolAddress((void**)&bufS, g_bufS);
    cudaGetSymbolAddress((void**)&bufP, g_bufP);
    cudaGetSymbolAddress((void**)&bufQ, g_bufQ);
    cudaGetSymbolAddress((void**)&bufB, g_bufB);
    cudaGetSymbolAddress((void**)&hs,   g_hs);
    cudaGetSymbolAddress((void**)&ls,   g_ls);
    cudaGetSymbolAddress((void**)&work, g_work);
    cudaGetSymbolAddress((void**)&offs, g_offs);
    cudaGetSymbolAddress((void**)&csr,  g_csr);
    cudaGetSymbolAddress((void**)&dinv, g_dinv);
    cudaGetSymbolAddress((void**)&pool, g_pool);
    cudaGetSymbolAddress((void**)&xc,   g_xc);
    cudaGetSymbolAddress((void**)&t0,   g_t0);
    cudaGetSymbolAddress((void**)&t1,   g_t1);
    cudaGetSymbolAddress((void**)&part, g_part);

    float* partA = part;                 // branch + head MLP (stream 0)
    float* partB = part + (2 << 20);     // cell MLP (stream s2)

    static cudaStream_t s1 = nullptr, s2 = nullptr;
    static cudaEvent_t evStart, evH2, evBranch, evCell, evZero;
    if (!s1) {
        cudaStreamCreateWithFlags(&s1, cudaStreamNonBlocking);
        cudaStreamCreateWithFlags(&s2, cudaStreamNonBlocking);
        cudaEventCreateWithFlags(&evStart, cudaEventDisableTiming);
        cudaEventCreateWithFlags(&evH2, cudaEventDisableTiming);
        cudaEventCreateWithFlags(&evBranch, cudaEventDisableTiming);
        cudaEventCreateWithFlags(&evCell, cudaEventDisableTiming);
        cudaEventCreateWithFlags(&evZero, cudaEventDisableTiming);
    }

    const int EB = (EE + 255) / 256;
    const int HAGG = (NN * 32 + 255) / 256;
    const int PREPB = (NN * 80 + 255) / 256;
    const int POOLB = ((NN / 32) * 312 + 255) / 256;

    // ======== fork ========
    cudaEventRecord(evStart, 0);

    // ======== stream s2: cell MLP from t=0 ========
    cudaStreamWaitEvent(s2, evStart, 0);
    k_norm<<<GG, 256, 0, s2>>>(cell, t0);
    tgemm(t0, 960, Wr1, br1, t1, 2048, GG, 2048, 960, 954, 2, true, partB, s2);
    tgemm(t1, 2048, Wr2, br2, t0, 512, GG, 512, 2048, 2048, 8, true, partB, s2);
    tgemm(t0, 512, Wr3, br3, xc + 256, 512, GG, 256, 512, 512, 4, true, partB, s2);
    cudaEventRecord(evCell, s2);

    // ======== per-half full chains (h0 on stream 0, h1 on s1) ========
    cudaStreamWaitEvent(s1, evStart, 0);
    for (int h = 0; h < 2; h++) {
        cudaStream_t st = h ? s1 : 0;
        const float* x  = h ? x2 : x1;
        const int* ei   = h ? ei2 : ei1;
        const int* bat  = h ? bat2 : bat1;
        int* cnt_h  = work + h * NN;
        int* fill_h = work + N2 + h * NN;
        int* offs_h = offs + h * (NN + 1);
        int* csr_h  = csr + h * EE;
        float* dinv_h = dinv + h * NN;
        float* bufS_h = bufS + (size_t)h * NN * 80;
        float* bufP_h = bufP + (size_t)h * NN * 80;
        float* bufQ_h = bufQ + (size_t)h * NN * 160;
        float* bufB_h = bufB + (size_t)h * NN * 312;
        uint32_t* hs_h = hs + (size_t)h * NN * 80;
        uint32_t* ls_h = ls + (size_t)h * NN * 80;
        float* pool_h = pool + (size_t)h * GG * 320;

        k_count_h<<<EB, 256, 0, st>>>(ei, cnt_h);
        k_scan_h<<<1, 1024, 0, st>>>(cnt_h, offs_h, dinv_h);
        k_fill_h<<<EB, 256, 0, st>>>(ei, offs_h, fill_h, csr_h);
        k_prep_h<<<PREPB, 256, 0, st>>>(x, dinv_h, bufS_h);

        k_agg_bf<40, 80><<<HAGG, 256, 0, st>>>(bufS_h, offs_h, csr_h, dinv_h, hs_h, ls_h);
        gemm_node(hs_h, ls_h, 40, Wc1, bc1, dinv_h, bufP_h, 80, NN, 78, 80, 78, true, st);
        k_agg_bf<40, 80><<<HAGG, 256, 0, st>>>(bufP_h, offs_h, csr_h, dinv_h, hs_h, ls_h);
        gemm_node(hs_h, ls_h, 40, Wc2, bc2, dinv_h, bufQ_h, 160, NN, 156, 80, 78, true, st);
        k_agg_bf<80, 160><<<HAGG, 256, 0, st>>>(bufQ_h, offs_h, csr_h, dinv_h, hs_h, ls_h);
        gemm_node(hs_h, ls_h, 80, Wc3, bc3, dinv_h, bufB_h, 312, NN, 312, 160, 156, false, st);

        k_pool_h<<<POOLB, 256, 0, st>>>(bufB_h, bat, pool_h);
    }
    cudaEventRecord(evH2, s1);
    cudaStreamWaitEvent(0, evH2, 0);

    // ---- branch MLP batched (M = 512)
    float* tb0 = t0 + GG * 2048;
    tgemm(pool, 320, Wg1, bg1, tb0, 160, 2 * GG, 156, 320, 312, 4, true, partA, 0);
    cudaEventRecord(evBranch, 0);
    // Wg2: partials (S=8) then fused reduce+scatter into xc
    {
        int Kp = 160, S = 8;
        int Kc = ((Kp / S + 15) / 16) * 16;
        if (Kc < 16) Kc = 16;
        int Se = (Kp + Kc - 1) / Kc;
        dim3 grid((128 + 63) / 64, (2 * GG + 127) / 128, Se);
        k_tgemm<false, false, true, false><<<grid, 256>>>(tb0, 160, nullptr, nullptr, 0, Wg2, nullptr, nullptr, partA, 0, 2 * GG, 128, Kp, 156, Kc);
        k_reduce_scat<<<(2 * GG * 128 + 255) / 256, 256>>>(partA, Se, bg2, xc);
    }

    // ======== stream s2: zero work+pool after branch MLP consumed pool ========
    cudaStreamWaitEvent(s2, evBranch, 0);
    k_zero<<<(2 * GG * 320 + 255) / 256, 256, 0, s2>>>(work, pool);
    cudaEventRecord(evZero, s2);

    // ======== stream 0: head MLP ========
    cudaStreamWaitEvent(0, evCell, 0);
    tgemm(xc, 512, Wf1, bf1, t0, 1024, GG, 1024, 512, 512, 4, true, partA, 0);
    tgemm(t0, 1024, Wf2, bf2, t1, 512, GG, 512, 1024, 1024, 8, true, partA, 0);
    tgemm(t1, 512, Wf3, bf3, t0, 128, GG, 128, 512, 512, 16, true, partA, 0);
    k_wo<<<(GG * 2 + 255) / 256, 256>>>(t0, Wo, bo, out);

    // ---- join
    cudaStreamWaitEvent(0, evZero, 0);
}

// round 14
// speedup vs baseline: 1.3281x; 1.0336x over previous
#include <cuda_runtime.h>
#include <cuda_bf16.h>
#include <cstdint>

#define NN 20000
#define EE 320000
#define GG 256
#define N2 (2 * NN)
#define E2 (2 * EE)

// -------- scratch (static device globals; zero-init, no runtime allocation) --------
__device__ float    g_bufS[(N2 + 256) * 80];
__device__ float    g_bufP[(N2 + 256) * 80];
__device__ float    g_bufQ[(N2 + 256) * 160];
__device__ float    g_bufB[(N2 + 256) * 312];
__device__ uint32_t g_hs[(N2 + 256) * 80];
__device__ uint32_t g_ls[(N2 + 256) * 80];
__device__ int      g_work[2 * N2];
__device__ int      g_offs[2 * (NN + 1)];
__device__ int      g_csr[E2];
__device__ float    g_dinv[N2];
__device__ float    g_pool[2 * GG * 320];
__device__ float    g_xc[GG * 512];
__device__ float    g_t0[2 * GG * 2048];
__device__ float    g_t1[2 * GG * 2048];
__device__ float    g_part[4 * 1048576];

// -------- bf16 split helpers --------
__device__ __forceinline__ void bsplit2(float x, float y, uint32_t& hi, uint32_t& lo) {
    __nv_bfloat162 h = __floats2bfloat162_rn(x, y);
    float rx = x - __bfloat162float(h.x);
    float ry = y - __bfloat162float(h.y);
    __nv_bfloat162 l = __floats2bfloat162_rn(rx, ry);
    hi = *reinterpret_cast<uint32_t*>(&h);
    lo = *reinterpret_cast<uint32_t*>(&l);
}
__device__ __forceinline__ void mma16(float* c, const uint32_t* a, const uint32_t* b) {
    asm("mma.sync.aligned.m16n8k16.row.col.f32.bf16.bf16.f32 "
        "{%0,%1,%2,%3}, {%4,%5,%6,%7}, {%8,%9}, {%0,%1,%2,%3};"
        : "+f"(c[0]), "+f"(c[1]), "+f"(c[2]), "+f"(c[3])
        : "r"(a[0]), "r"(a[1]), "r"(a[2]), "r"(a[3]), "r"(b[0]), "r"(b[1]));
}

// -------- per-half CSR build --------
__global__ void k_count_h(const int* __restrict__ ei, int* __restrict__ cnt) {
    int e = blockIdx.x * blockDim.x + threadIdx.x;
    if (e < EE) atomicAdd(&cnt[ei[EE + e]], 1);
}

__global__ void k_scan_h(const int* __restrict__ cnt, int* __restrict__ offs,
                         float* __restrict__ dinv) {
    const int T = 1024;
    const int IPT = (NN + T - 1) / T;
    __shared__ int s[T];
    int tid = threadIdx.x;
    int base = tid * IPT;
    int local = 0;
    #pragma unroll
    for (int i = 0; i < IPT; i++) {
        int idx = base + i;
        if (idx < NN) {
            int c = cnt[idx];
            local += c;
            dinv[idx] = rsqrtf((float)(c + 1));
        }
    }
    s[tid] = local;
    __syncthreads();
    for (int off = 1; off < T; off <<= 1) {
        int v = 0;
        if (tid >= off) v = s[tid - off];
        __syncthreads();
        if (tid >= off) s[tid] += v;
        __syncthreads();
    }
    int run = (tid == 0) ? 0 : s[tid - 1];
    #pragma unroll
    for (int i = 0; i < IPT; i++) {
        int idx = base + i;
        if (idx < NN) { offs[idx] = run; run += cnt[idx]; }
    }
    if (tid == 0) offs[NN] = s[T - 1];
}

__global__ void k_fill_h(const int* __restrict__ ei, const int* __restrict__ offs,
                         int* __restrict__ fill, int* __restrict__ csr) {
    int e = blockIdx.x * blockDim.x + threadIdx.x;
    if (e >= EE) return;
    int s = ei[e], d = ei[EE + e];
    int p = atomicAdd(&fill[d], 1);
    csr[offs[d] + p] = s;
}

// -------- per-half prep --------
__global__ void k_prep_h(const float* __restrict__ x, const float* __restrict__ dinv,
                         float* __restrict__ out) {
    int i = blockIdx.x * blockDim.x + threadIdx.x;
    if (i >= NN * 80) return;
    int n = i / 80, f = i - n * 80;
    out[i] = (f < 78) ? dinv[n] * x[(size_t)n * 78 + f] : 0.f;
}

// -------- per-half prescaled aggregation -> bf16 hi/lo planes --------
template <int PAIRS, int LDI>
__global__ void k_agg_bf(const float* __restrict__ hp, const int* __restrict__ offs,
                         const int* __restrict__ csr, const float* __restrict__ dinv,
                         uint32_t* __restrict__ hi, uint32_t* __restrict__ lo) {
    const int R = (PAIRS + 31) / 32;
    int warp = (blockIdx.x * blockDim.x + threadIdx.x) >> 5;
    int lane = threadIdx.x & 31;
    if (warp >= NN) return;
    int n = warp;
    const float2* pn = (const float2*)(hp + (size_t)n * LDI);
    float2 acc[R];
    #pragma unroll
    for (int r = 0; r < R; r++) {
        int idx = lane + 32 * r;
        acc[r] = (idx < PAIRS) ? pn[idx] : make_float2(0.f, 0.f);
    }
    int e0 = offs[n], e1 = offs[n + 1];
    int e = e0;
    for (; e + 4 <= e1; e += 4) {
        const float2* p0 = (const float2*)(hp + (size_t)csr[e] * LDI);
        const float2* p1 = (const float2*)(hp + (size_t)csr[e + 1] * LDI);
        const float2* p2 = (const float2*)(hp + (size_t)csr[e + 2] * LDI);
        const float2* p3 = (const float2*)(hp + (size_t)csr[e + 3] * LDI);
        #pragma unroll
        for (int r = 0; r < R; r++) {
            int idx = lane + 32 * r;
            if (idx < PAIRS) {
                float2 a = p0[idx], b = p1[idx], c = p2[idx], d = p3[idx];
                acc[r].x += (a.x + b.x) + (c.x + d.x);
                acc[r].y += (a.y + b.y) + (c.y + d.y);
            }
        }
    }
    for (; e < e1; e++) {
        const float2* p0 = (const float2*)(hp + (size_t)csr[e] * LDI);
        #pragma unroll
        for (int r = 0; r < R; r++) {
            int idx = lane + 32 * r;
            if (idx < PAIRS) {
                float2 a = p0[idx];
                acc[r].x += a.x;
                acc[r].y += a.y;
            }
        }
    }
    float din = dinv[n];
    #pragma unroll
    for (int r = 0; r < R; r++) {
        int idx = lane + 32 * r;
        if (idx < PAIRS) {
            uint32_t h, l;
            bsplit2(din * acc[r].x, din * acc[r].y, h, l);
            hi[(size_t)n * PAIRS + idx] = h;
            lo[(size_t)n * PAIRS + idx] = l;
        }
    }
}

// -------- per-half global max pool --------
__global__ void k_pool_h(const float* __restrict__ h, const int* __restrict__ bat,
                         float* __restrict__ pool) {
    const int CH = 32;
    const int NCH = NN / CH;
    int idx = blockIdx.x * blockDim.x + threadIdx.x;
    if (idx >= NCH * 312) return;
    int f = idx % 312;
    int c = idx / 312;
    int n0 = c * CH;
    int n1 = n0 + CH;
    int curb = bat[n0];
    float m = 0.f;
    for (int n = n0; n < n1; n++) {
        int b = bat[n];
        if (b != curb) {
            atomicMax((int*)&pool[curb * 320 + f], __float_as_int(m));
            curb = b;
            m = 0.f;
        }
        m = fmaxf(m, h[(size_t)n * 312 + f]);
    }
    atomicMax((int*)&pool[curb * 320 + f], __float_as_int(m));
}

// -------- L2 row normalize -> ld 960 --------
__global__ void k_norm(const float* __restrict__ cell, float* __restrict__ out) {
    int g = blockIdx.x;
    __shared__ float s[256];
    float ss = 0.f;
    for (int j = threadIdx.x; j < 954; j += 256) {
        float v = cell[g * 954 + j];
        ss += v * v;
    }
    s[threadIdx.x] = ss;
    __syncthreads();
    for (int o = 128; o > 0; o >>= 1) {
        if (threadIdx.x < o) s[threadIdx.x] += s[threadIdx.x + o];
        __syncthreads();
    }
    float inv = 1.f / fmaxf(sqrtf(s[0]), 1e-12f);
    for (int j = threadIdx.x; j < 960; j += 256)
        out[g * 960 + j] = (j < 954) ? cell[g * 954 + j] * inv : 0.f;
}

// -------- zero kernel --------
__global__ void k_zero(int* __restrict__ work, float* __restrict__ pool) {
    int i = blockIdx.x * blockDim.x + threadIdx.x;
    if (i < 2 * N2) work[i] = 0;
    if (i < 2 * GG * 320) pool[i] = 0.f;
}

// ======== tensor-core GEMM: bf16x3 on mma.m16n8k16, interleaved hi/lo smem ========
template <bool RELU, bool PRESCALE, bool SPLITK, bool ASPLIT>
__global__ __launch_bounds__(256)
void k_tgemm(const float* __restrict__ A, int lda,
             const uint32_t* __restrict__ hiA, const uint32_t* __restrict__ loA, int ldu,
             const float* __restrict__ B,
             const float* __restrict__ bias,
             const float* __restrict__ dinv,
             float* __restrict__ C, int ldc,
             int M, int N, int Kp, int Kr, int Kc) {
    const int BM = 128, BN = 64;
    __shared__ uint2 Ahl[2][8][BM + 4];   // .x = hi plane, .y = lo plane (bf16x2 each)
    __shared__ uint2 Bhl[2][8][BN + 4];
    int tid = threadIdx.x;
    int lane = tid & 31, wid = tid >> 5;
    int gid = lane >> 2, tq = lane & 3;
    int wm = (wid & 3) * 32, wn = (wid >> 2) * 32;
    int m0 = blockIdx.y * BM, n0 = blockIdx.x * BN;
    int kbeg = SPLITK ? blockIdx.z * Kc : 0;
    int kend = SPLITK ? min(Kp, kbeg + Kc) : Kp;

    int arow = tid & 127;
    int akp = (tid >> 7) * 4;
    const float* Ar = ASPLIT ? nullptr : A + (size_t)(m0 + arow) * lda + kbeg;
    const uint32_t* HiR = ASPLIT ? hiA + (size_t)(m0 + arow) * ldu + (kbeg >> 1) : nullptr;
    const uint32_t* LoR = ASPLIT ? loA + (size_t)(m0 + arow) * ldu + (kbeg >> 1) : nullptr;
    int bn = tid & 63;
    int bkp = tid >> 6;

    float acc[2][4][4];
    #pragma unroll
    for (int i = 0; i < 2; i++)
        #pragma unroll
        for (int j = 0; j < 4; j++)
            #pragma unroll
            for (int r = 0; r < 4; r++) acc[i][j][r] = 0.f;

    int ksteps = (kend - kbeg) / 16;

    {   // prologue
        if (ASPLIT) {
            uint4 h4 = *(const uint4*)(HiR + akp);
            uint4 l4 = *(const uint4*)(LoR + akp);
            Ahl[0][akp + 0][arow] = make_uint2(h4.x, l4.x);
            Ahl[0][akp + 1][arow] = make_uint2(h4.y, l4.y);
            Ahl[0][akp + 2][arow] = make_uint2(h4.z, l4.z);
            Ahl[0][akp + 3][arow] = make_uint2(h4.w, l4.w);
        } else {
            float4 a0 = *(const float4*)(Ar + akp * 2);
            float4 a1 = *(const float4*)(Ar + akp * 2 + 4);
            uint32_t h, l;
            bsplit2(a0.x, a0.y, h, l); Ahl[0][akp + 0][arow] = make_uint2(h, l);
            bsplit2(a0.z, a0.w, h, l); Ahl[0][akp + 1][arow] = make_uint2(h, l);
            bsplit2(a1.x, a1.y, h, l); Ahl[0][akp + 2][arow] = make_uint2(h, l);
            bsplit2(a1.z, a1.w, h, l); Ahl[0][akp + 3][arow] = make_uint2(h, l);
        }
        #pragma unroll
        for (int h2 = 0; h2 < 2; h2++) {
            int kp = bkp + 4 * h2;
            int k = kbeg + 2 * kp;
            int nn = n0 + bn;
            float f0 = (k < Kr && nn < N) ? B[(size_t)k * N + nn] : 0.f;
            float f1 = (k + 1 < Kr && nn < N) ? B[(size_t)(k + 1) * N + nn] : 0.f;
            uint32_t h, l;
            bsplit2(f0, f1, h, l);
            Bhl[0][kp][bn] = make_uint2(h, l);
        }
    }
    __syncthreads();

    for (int t = 0; t < ksteps; t++) {
        int cur = t & 1;
        bool more = (t + 1 < ksteps);
        float4 pa0, pa1;
        uint4 ph4, pl4;
        float pb[2][2];
        if (more) {
            if (ASPLIT) {
                ph4 = *(const uint4*)(HiR + (t + 1) * 8 + akp);
                pl4 = *(const uint4*)(LoR + (t + 1) * 8 + akp);
            } else {
                int k0 = (t + 1) * 16;
                pa0 = *(const float4*)(Ar + k0 + akp * 2);
                pa1 = *(const float4*)(Ar + k0 + akp * 2 + 4);
            }
            #pragma unroll
            for (int h2 = 0; h2 < 2; h2++) {
                int k = kbeg + (t + 1) * 16 + 2 * (bkp + 4 * h2);
                int nn = n0 + bn;
                pb[h2][0] = (k < Kr && nn < N) ? B[(size_t)k * N + nn] : 0.f;
                pb[h2][1] = (k + 1 < Kr && nn < N) ? B[(size_t)(k + 1) * N + nn] : 0.f;
            }
        }

        uint32_t ah[2][4], al[2][4], bh[4][2], bl[4][2];
        #pragma unroll
        for (int mi = 0; mi < 2; mi++) {
            int r = wm + mi * 16 + gid;
            uint2 v0 = Ahl[cur][tq][r];
            uint2 v1 = Ahl[cur][tq][r + 8];
            uint2 v2 = Ahl[cur][tq + 4][r];
            uint2 v3 = Ahl[cur][tq + 4][r + 8];
            ah[mi][0] = v0.x; al[mi][0] = v0.y;
            ah[mi][1] = v1.x; al[mi][1] = v1.y;
            ah[mi][2] = v2.x; al[mi][2] = v2.y;
            ah[mi][3] = v3.x; al[mi][3] = v3.y;
        }
        #pragma unroll
        for (int ni = 0; ni < 4; ni++) {
            int c = wn + ni * 8 + gid;
            uint2 w0 = Bhl[cur][tq][c];
            uint2 w1 = Bhl[cur][tq + 4][c];
            bh[ni][0] = w0.x; bl[ni][0] = w0.y;
            bh[ni][1] = w1.x; bl[ni][1] = w1.y;
        }
        #pragma unroll
        for (int mi = 0; mi < 2; mi++)
            #pragma unroll
            for (int ni = 0; ni < 4; ni++) {
                mma16(acc[mi][ni], ah[mi], bh[ni]);
                mma16(acc[mi][ni], al[mi], bh[ni]);
                mma16(acc[mi][ni], ah[mi], bl[ni]);
            }

        if (more) {
            int nxt = cur ^ 1;
            if (ASPLIT) {
                Ahl[nxt][akp + 0][arow] = make_uint2(ph4.x, pl4.x);
                Ahl[nxt][akp + 1][arow] = make_uint2(ph4.y, pl4.y);
                Ahl[nxt][akp + 2][arow] = make_uint2(ph4.z, pl4.z);
                Ahl[nxt][akp + 3][arow] = make_uint2(ph4.w, pl4.w);
            } else {
                uint32_t h, l;
                bsplit2(pa0.x, pa0.y, h, l); Ahl[nxt][akp + 0][arow] = make_uint2(h, l);
                bsplit2(pa0.z, pa0.w, h, l); Ahl[nxt][akp + 1][arow] = make_uint2(h, l);
                bsplit2(pa1.x, pa1.y, h, l); Ahl[nxt][akp + 2][arow] = make_uint2(h, l);
                bsplit2(pa1.z, pa1.w, h, l); Ahl[nxt][akp + 3][arow] = make_uint2(h, l);
            }
            #pragma unroll
            for (int h2 = 0; h2 < 2; h2++) {
                int kp = bkp + 4 * h2;
                uint32_t h, l;
                bsplit2(pb[h2][0], pb[h2][1], h, l);
                Bhl[nxt][kp][bn] = make_uint2(h, l);
            }
            __syncthreads();
        }
    }

    #pragma unroll
    for (int mi = 0; mi < 2; mi++) {
        int r0 = m0 + wm + mi * 16 + gid;
        int r1 = r0 + 8;
        float d0 = 1.f, d1 = 1.f;
        if (PRESCALE) {
            if (r0 < M) d0 = dinv[r0];
            if (r1 < M) d1 = dinv[r1];
        }
        #pragma unroll
        for (int ni = 0; ni < 4; ni++) {
            int cc = n0 + wn + ni * 8 + 2 * tq;
            if (cc >= N) continue;
            float* a = acc[mi][ni];
            if (SPLITK) {
                size_t base = (size_t)blockIdx.z * M * N;
                if (r0 < M) *(float2*)&C[base + (size_t)r0 * N + cc] = make_float2(a[0], a[1]);
                if (r1 < M) *(float2*)&C[base + (size_t)r1 * N + cc] = make_float2(a[2], a[3]);
            } else {
                float b0 = bias[cc], b1 = bias[cc + 1];
                float v00 = a[0] + b0, v01 = a[1] + b1;
                float v10 = a[2] + b0, v11 = a[3] + b1;
                if (RELU) {
                    v00 = fmaxf(v00, 0.f); v01 = fmaxf(v01, 0.f);
                    v10 = fmaxf(v10, 0.f); v11 = fmaxf(v11, 0.f);
                }
                if (PRESCALE) { v00 *= d0; v01 *= d0; v10 *= d1; v11 *= d1; }
                if (r0 < M) *(float2*)&C[(size_t)r0 * ldc + cc] = make_float2(v00, v01);
                if (r1 < M) *(float2*)&C[(size_t)r1 * ldc + cc] = make_float2(v10, v11);
            }
        }
    }
}

template <bool RELU>
__global__ void k_reduce(const float* __restrict__ part, int S,
                         const float* __restrict__ bias,
                         float* __restrict__ C, int ldc, int M, int N) {
    int i = blockIdx.x * blockDim.x + threadIdx.x;
    if (i >= M * N) return;
    int m = i / N, n = i % N;
    float v = 0.f;
    for (int s = 0; s < S; s++) v += part[(size_t)s * M * N + i];
    v += bias[n];
    if (RELU) v = fmaxf(v, 0.f);
    C[m * ldc + n] = v;
}

// reduce Wg2 partials [2G,128] and scatter into xc[G,512] in one pass
__global__ void k_reduce_scat(const float* __restrict__ part, int S,
                              const float* __restrict__ bias,
                              float* __restrict__ xc) {
    int i = blockIdx.x * blockDim.x + threadIdx.x;
    if (i >= 2 * GG * 128) return;
    int m = i >> 7, j = i & 127;
    float v = 0.f;
    for (int s = 0; s < S; s++) v += part[(size_t)s * 2 * GG * 128 + i];
    v += bias[j];
    int g = m & 255, br = m >> 8;
    xc[g * 512 + br * 128 + j] = v;
}

static void gemm_node(const uint32_t* hiA, const uint32_t* loA, int ldu,
                      const float* B, const float* bias, const float* dinv,
                      float* C, int ldc, int M, int N, int Kp, int Kr, bool prescale,
                      cudaStream_t st) {
    dim3 grid((N + 63) / 64, (M + 127) / 128);
    if (prescale)
        k_tgemm<true, true, false, true><<<grid, 256, 0, st>>>(nullptr, 0, hiA, loA, ldu, B, bias, dinv, C, ldc, M, N, Kp, Kr, Kp);
    else
        k_tgemm<true, false, false, true><<<grid, 256, 0, st>>>(nullptr, 0, hiA, loA, ldu, B, bias, dinv, C, ldc, M, N, Kp, Kr, Kp);
}

static void tgemm(const float* A, int lda, const float* B, const float* bias,
                  float* C, int ldc, int M, int N, int Kp, int Kr,
                  int S, bool relu, float* part, cudaStream_t st, bool reduce = true) {
    if (S <= 1) {
        dim3 grid((N + 63) / 64, (M + 127) / 128);
        if (relu)
            k_tgemm<true, false, false, false><<<grid, 256, 0, st>>>(A, lda, nullptr, nullptr, 0, B, bias, nullptr, C, ldc, M, N, Kp, Kr, Kp);
        else
            k_tgemm<false, false, false, false><<<grid, 256, 0, st>>>(A, lda, nullptr, nullptr, 0, B, bias, nullptr, C, ldc, M, N, Kp, Kr, Kp);
        return;
    }
    int Kc = ((Kp / S + 15) / 16) * 16;
    if (Kc < 16) Kc = 16;
    int Se = (Kp + Kc - 1) / Kc;
    dim3 grid((N + 63) / 64, (M + 127) / 128, Se);
    k_tgemm<false, false, true, false><<<grid, 256, 0, st>>>(A, lda, nullptr, nullptr, 0, B, nullptr, nullptr, part, 0, M, N, Kp, Kr, Kc);
    if (reduce) {
        int tot = M * N;
        if (relu) k_reduce<true><<<(tot + 255) / 256, 256, 0, st>>>(part, Se, bias, C, ldc, M, N);
        else      k_reduce<false><<<(tot + 255) / 256, 256, 0, st>>>(part, Se, bias, C, ldc, M, N);
    }
}

// -------- tiny scalar GEMM for the final 256x2x128 --------
__global__ void k_wo(const float* __restrict__ A, const float* __restrict__ B,
                     const float* __restrict__ bias, float* __restrict__ C) {
    int g = blockIdx.x * blockDim.x + threadIdx.x;
    if (g >= GG * 2) return;
    int m = g >> 1, n = g & 1;
    float v = 0.f;
    const float* a = A + m * 128;
    for (int k = 0; k < 128; k++) v += a[k] * B[k * 2 + n];
    C[g] = v + bias[n];
}

extern "C" void kernel_launch(void* const* d_in, const int* in_sizes, int n_in,
                              void* d_out, int out_size) {
    const float* x1   = (const float*)d_in[0];
    const int*   ei1  = (const int*)d_in[1];
    const int*   bat1 = (const int*)d_in[2];
    const float* x2   = (const float*)d_in[3];
    const int*   ei2  = (const int*)d_in[4];
    const int*   bat2 = (const int*)d_in[5];
    const float* cell = (const float*)d_in[6];
    const float* Wc1 = (const float*)d_in[7];  const float* bc1 = (const float*)d_in[8];
    const float* Wc2 = (const float*)d_in[9];  const float* bc2 = (const float*)d_in[10];
    const float* Wc3 = (const float*)d_in[11]; const float* bc3 = (const float*)d_in[12];
    const float* Wg1 = (const float*)d_in[13]; const float* bg1 = (const float*)d_in[14];
    const float* Wg2 = (const float*)d_in[15]; const float* bg2 = (const float*)d_in[16];
    const float* Wr1 = (const float*)d_in[17]; const float* br1 = (const float*)d_in[18];
    const float* Wr2 = (const float*)d_in[19]; const float* br2 = (const float*)d_in[20];
    const float* Wr3 = (const float*)d_in[21]; const float* br3 = (const float*)d_in[22];
    const float* Wf1 = (const float*)d_in[23]; const float* bf1 = (const float*)d_in[24];
    const float* Wf2 = (const float*)d_in[25]; const float* bf2 = (const float*)d_in[26];
    const float* Wf3 = (const float*)d_in[27]; const float* bf3 = (const float*)d_in[28];
    const float* Wo  = (const float*)d_in[29]; const float* bo  = (const float*)d_in[30];
    float* out = (float*)d_out;

    float *bufS, *bufP, *bufQ, *bufB, *dinv, *pool, *xc, *t0, *t1, *part;
    uint32_t *hs, *ls;
    int *work, *offs, *csr;
    cudaGetSymbolAddress((void**)&bufS, g_bufS);
    cudaGetSymbolAddress((void**)&bufP, g_bufP);
    cudaGetSymbolAddress((void**)&bufQ, g_bufQ);
    cudaGetSymbolAddress((void**)&bufB, g_bufB);
    cudaGetSymbolAddress((void**)&hs,   g_hs);
    cudaGetSymbolAddress((void**)&ls,   g_ls);
    cudaGetSymbolAddress((void**)&work, g_work);
    cudaGetSymbolAddress((void**)&offs, g_offs);
    cudaGetSymbolAddress((void**)&csr,  g_csr);
    cudaGetSymbolAddress((void**)&dinv, g_dinv);
    cudaGetSymbolAddress((void**)&pool, g_pool);
    cudaGetSymbolAddress((void**)&xc,   g_xc);
    cudaGetSymbolAddress((void**)&t0,   g_t0);
    cudaGetSymbolAddress((void**)&t1,   g_t1);
    cudaGetSymbolAddress((void**)&part, g_part);

    float* partA = part;                 // branch + head MLP (stream 0), 2M floats
    float* partB = part + (2 << 20);     // cell MLP (stream s2), 2M floats

    static cudaStream_t s1 = nullptr, s2 = nullptr;
    static cudaEvent_t evStart, evH2, evBranch, evCell, evZero;
    if (!s1) {
        cudaStreamCreateWithFlags(&s1, cudaStreamNonBlocking);
        cudaStreamCreateWithFlags(&s2, cudaStreamNonBlocking);
        cudaEventCreateWithFlags(&evStart, cudaEventDisableTiming);
        cudaEventCreateWithFlags(&evH2, cudaEventDisableTiming);
        cudaEventCreateWithFlags(&evBranch, cudaEventDisableTiming);
        cudaEventCreateWithFlags(&evCell, cudaEventDisableTiming);
        cudaEventCreateWithFlags(&evZero, cudaEventDisableTiming);
    }

    const int EB = (EE + 255) / 256;
    const int HAGG = (NN * 32 + 255) / 256;
    const int PREPB = (NN * 80 + 255) / 256;
    const int POOLB = ((NN / 32) * 312 + 255) / 256;

    // ======== fork ========
    cudaEventRecord(evStart, 0);

    // ======== stream s2: cell MLP from t=0 ========
    cudaStreamWaitEvent(s2, evStart, 0);
    k_norm<<<GG, 256, 0, s2>>>(cell, t0);
    tgemm(t0, 960, Wr1, br1, t1, 2048, GG, 2048, 960, 954, 4, true, partB, s2);
    tgemm(t1, 2048, Wr2, br2, t0, 512, GG, 512, 2048, 2048, 16, true, partB, s2);
    tgemm(t0, 512, Wr3, br3, xc + 256, 512, GG, 256, 512, 512, 16, true, partB, s2);
    cudaEventRecord(evCell, s2);

    // ======== per-half full chains (h0 on stream 0, h1 on s1) ========
    cudaStreamWaitEvent(s1, evStart, 0);
    for (int h = 0; h < 2; h++) {
        cudaStream_t st = h ? s1 : 0;
        const float* x  = h ? x2 : x1;
        const int* ei   = h ? ei2 : ei1;
        const int* bat  = h ? bat2 : bat1;
        int* cnt_h  = work + h * NN;
        int* fill_h = work + N2 + h * NN;
        int* offs_h = offs + h * (NN + 1);
        int* csr_h  = csr + h * EE;
        float* dinv_h = dinv + h * NN;
        float* bufS_h = bufS + (size_t)h * NN * 80;
        float* bufP_h = bufP + (size_t)h * NN * 80;
        float* bufQ_h = bufQ + (size_t)h * NN * 160;
        float* bufB_h = bufB + (size_t)h * NN * 312;
        uint32_t* hs_h = hs + (size_t)h * NN * 80;
        uint32_t* ls_h = ls + (size_t)h * NN * 80;
        float* pool_h = pool + (size_t)h * GG * 320;

        k_count_h<<<EB, 256, 0, st>>>(ei, cnt_h);
        k_scan_h<<<1, 1024, 0, st>>>(cnt_h, offs_h, dinv_h);
        k_fill_h<<<EB, 256, 0, st>>>(ei, offs_h, fill_h, csr_h);
        k_prep_h<<<PREPB, 256, 0, st>>>(x, dinv_h, bufS_h);

        k_agg_bf<40, 80><<<HAGG, 256, 0, st>>>(bufS_h, offs_h, csr_h, dinv_h, hs_h, ls_h);
        gemm_node(hs_h, ls_h, 40, Wc1, bc1, dinv_h, bufP_h, 80, NN, 78, 80, 78, true, st);
        k_agg_bf<40, 80><<<HAGG, 256, 0, st>>>(bufP_h, offs_h, csr_h, dinv_h, hs_h, ls_h);
        gemm_node(hs_h, ls_h, 40, Wc2, bc2, dinv_h, bufQ_h, 160, NN, 156, 80, 78, true, st);
        k_agg_bf<80, 160><<<HAGG, 256, 0, st>>>(bufQ_h, offs_h, csr_h, dinv_h, hs_h, ls_h);
        gemm_node(hs_h, ls_h, 80, Wc3, bc3, dinv_h, bufB_h, 312, NN, 312, 160, 156, false, st);

        k_pool_h<<<POOLB, 256, 0, st>>>(bufB_h, bat, pool_h);
    }
    cudaEventRecord(evH2, s1);
    cudaStreamWaitEvent(0, evH2, 0);

    // ---- branch MLP batched (M = 512)
    float* tb0 = t0 + GG * 2048;
    tgemm(pool, 320, Wg1, bg1, tb0, 160, 2 * GG, 156, 320, 312, 8, true, partA, 0);
    cudaEventRecord(evBranch, 0);
    // Wg2: partials (S=8) then fused reduce+scatter into xc
    {
        int Kp = 160, S = 8;
        int Kc = ((Kp / S + 15) / 16) * 16;
        if (Kc < 16) Kc = 16;
        int Se = (Kp + Kc - 1) / Kc;
        dim3 grid((128 + 63) / 64, (2 * GG + 127) / 128, Se);
        k_tgemm<false, false, true, false><<<grid, 256>>>(tb0, 160, nullptr, nullptr, 0, Wg2, nullptr, nullptr, partA, 0, 2 * GG, 128, Kp, 156, Kc);
        k_reduce_scat<<<(2 * GG * 128 + 255) / 256, 256>>>(partA, Se, bg2, xc);
    }

    // ======== stream s2: zero work+pool after branch MLP consumed pool ========
    cudaStreamWaitEvent(s2, evBranch, 0);
    k_zero<<<(2 * GG * 320 + 255) / 256, 256, 0, s2>>>(work, pool);
    cudaEventRecord(evZero, s2);

    // ======== stream 0: head MLP ========
    cudaStreamWaitEvent(0, evCell, 0);
    tgemm(xc, 512, Wf1, bf1, t0, 1024, GG, 1024, 512, 512, 8, true, partA, 0);
    tgemm(t0, 1024, Wf2, bf2, t1, 512, GG, 512, 1024, 1024, 16, true, partA, 0);
    tgemm(t1, 512, Wf3, bf3, t0, 128, GG, 128, 512, 512, 16, true, partA, 0);
    k_wo<<<(GG * 2 + 255) / 256, 256>>>(t0, Wo, bo, out);

    // ---- join
    cudaStreamWaitEvent(0, evZero, 0);
}